// round 2
// baseline (speedup 1.0000x reference)
#include <cuda_runtime.h>

// CTPN loss: H=512, W=1024, K=10, N_POS=N_NEG=64.
// Inputs (metadata order):
//  0 scores   [1,2K,H,W] f32     (2*10*512*1024)
//  1 vcoords  [1,2K,H,W] f32
//  2 sides    [1,K,H,W]  f32
//  3 pos_y [64] i32   4 pos_x [64] i32   5 pos_z [64] i32
//  6 neg_y [64] i32   7 neg_x [64] i32   8 neg_z [64] i32
//  9 v_targets [64,2] f32
// 10 side_mask [64] i32
// 11 side_targets [64] f32
// Output: 4 f32 = (loss, avg_loss_cls, avg_loss_reg_v, avg_loss_reg_o)

#define HW_ (512 * 1024)
#define W_  1024

__device__ __forceinline__ float smooth_l1(float d) {
    float a = fabsf(d);
    return (a < 1.0f) ? 0.5f * a * a : a - 0.5f;
}

__global__ void ctpn_loss_kernel(
    const float* __restrict__ scores,
    const float* __restrict__ vcoords,
    const float* __restrict__ sides,
    const int* __restrict__ pos_y, const int* __restrict__ pos_x, const int* __restrict__ pos_z,
    const int* __restrict__ neg_y, const int* __restrict__ neg_x, const int* __restrict__ neg_z,
    const float* __restrict__ v_targets,
    const int* __restrict__ side_mask,
    const float* __restrict__ side_targets,
    float* __restrict__ out, int out_size)
{
    const int tid = threadIdx.x;

    float cls = 0.0f, vsum = 0.0f, osum = 0.0f, cnt = 0.0f;

    if (tid < 64) {
        // positive anchor
        const int y = pos_y[tid], x = pos_x[tid], z = pos_z[tid];
        const long long base = (long long)(2 * z) * HW_ + (long long)y * W_ + x;

        // CE with target class 1: -log_softmax[1] = lse - s1 (stable)
        const float s0 = scores[base];
        const float s1 = scores[base + HW_];
        const float m  = fmaxf(s0, s1);
        const float lse = m + logf(expf(s0 - m) + expf(s1 - m));
        cls = lse - s1;

        // vertical coord SmoothL1 (both components)
        const float v0 = vcoords[base];
        const float v1 = vcoords[base + HW_];
        vsum = smooth_l1(v0 - v_targets[2 * tid])
             + smooth_l1(v1 - v_targets[2 * tid + 1]);

        // side refinement (masked)
        const float sp = sides[(long long)z * HW_ + (long long)y * W_ + x];
        const float mm = (float)side_mask[tid];
        osum = smooth_l1(sp - side_targets[tid]) * mm;
        cnt  = mm;
    } else {
        // negative anchor, CE with target class 0: lse - s0
        const int i = tid - 64;
        const int y = neg_y[i], x = neg_x[i], z = neg_z[i];
        const long long base = (long long)(2 * z) * HW_ + (long long)y * W_ + x;
        const float s0 = scores[base];
        const float s1 = scores[base + HW_];
        const float m  = fmaxf(s0, s1);
        const float lse = m + logf(expf(s0 - m) + expf(s1 - m));
        cls = lse - s0;
    }

    // block reduction over 128 threads, 4 accumulators
    __shared__ float sh0[128], sh1[128], sh2[128], sh3[128];
    sh0[tid] = cls; sh1[tid] = vsum; sh2[tid] = osum; sh3[tid] = cnt;
    __syncthreads();

    #pragma unroll
    for (int s = 64; s >= 32; s >>= 1) {
        if (tid < s) {
            sh0[tid] += sh0[tid + s];
            sh1[tid] += sh1[tid + s];
            sh2[tid] += sh2[tid + s];
            sh3[tid] += sh3[tid + s];
        }
        __syncthreads();
    }

    if (tid < 32) {
        float a = sh0[tid], b = sh1[tid], c = sh2[tid], d = sh3[tid];
        #pragma unroll
        for (int off = 16; off > 0; off >>= 1) {
            a += __shfl_down_sync(0xFFFFFFFFu, a, off);
            b += __shfl_down_sync(0xFFFFFFFFu, b, off);
            c += __shfl_down_sync(0xFFFFFFFFu, c, off);
            d += __shfl_down_sync(0xFFFFFFFFu, d, off);
        }
        if (tid == 0) {
            const float avg_cls = a * (1.0f / 128.0f);
            const float avg_v   = b * (1.0f / 128.0f);  // 64 anchors * 2 comps
            const float avg_o   = (d > 0.0f) ? c / fmaxf(d, 1.0f) : 0.0f;
            const float loss = avg_cls + 1.0f * avg_v + 2.0f * avg_o;
            if (out_size > 0) out[0] = loss;
            if (out_size > 1) out[1] = avg_cls;
            if (out_size > 2) out[2] = avg_v;
            if (out_size > 3) out[3] = avg_o;
        }
    }
}

extern "C" void kernel_launch(void* const* d_in, const int* in_sizes, int n_in,
                              void* d_out, int out_size) {
    const float* scores       = (const float*)d_in[0];
    const float* vcoords      = (const float*)d_in[1];
    const float* sides        = (const float*)d_in[2];
    const int*   pos_y        = (const int*)d_in[3];
    const int*   pos_x        = (const int*)d_in[4];
    const int*   pos_z        = (const int*)d_in[5];
    const int*   neg_y        = (const int*)d_in[6];
    const int*   neg_x        = (const int*)d_in[7];
    const int*   neg_z        = (const int*)d_in[8];
    const float* v_targets    = (const float*)d_in[9];
    const int*   side_mask    = (const int*)d_in[10];
    const float* side_targets = (const float*)d_in[11];

    ctpn_loss_kernel<<<1, 128>>>(scores, vcoords, sides,
                                 pos_y, pos_x, pos_z,
                                 neg_y, neg_x, neg_z,
                                 v_targets, side_mask, side_targets,
                                 (float*)d_out, out_size);
}